// round 2
// baseline (speedup 1.0000x reference)
#include <cuda_runtime.h>
#include <cuda_bf16.h>
#include <math.h>

// ---------------- problem constants ----------------
// B=8, C=2, H=256, W=64, PH=PW=4, HP=64, WP=16, N=1024, HID=1024,
// NH=16, HD=64, DEPTH=8, FFN=2730, TDIM=256, OUT=32
constexpr int   kFFN  = 2730;
constexpr float kEPS  = 1e-6f;

// ---------------- device scratch (single symbol, ~1.0 GB) ----------------
constexpr size_t SZ_TEMB = 8ULL * 256;
constexpr size_t SZ_CS   = 8ULL * 1024;
constexpr size_t SZ_ADA  = 8ULL * 6144;
constexpr size_t SZ_FADA = 8ULL * 2048;
constexpr size_t SZ_H    = 8192ULL * 1024;
constexpr size_t SZ_QKV  = 8192ULL * 3072;
constexpr size_t SZ_X12  = 8192ULL * 5460;
constexpr size_t SZ_G    = 8192ULL * 2730;
constexpr size_t SZ_Y    = 8192ULL * 32;
constexpr size_t SZ_SC   = 128ULL * 1024 * 1024;

constexpr size_t OFF_TEMB = 0;
constexpr size_t OFF_CS   = OFF_TEMB + SZ_TEMB;
constexpr size_t OFF_ADA  = OFF_CS   + SZ_CS;
constexpr size_t OFF_FADA = OFF_ADA  + SZ_ADA;
constexpr size_t OFF_H    = OFF_FADA + SZ_FADA;
constexpr size_t OFF_HN   = OFF_H    + SZ_H;
constexpr size_t OFF_QKV  = OFF_HN   + SZ_H;
constexpr size_t OFF_O    = OFF_QKV  + SZ_QKV;
constexpr size_t OFF_X12  = OFF_O    + SZ_H;
constexpr size_t OFF_G    = OFF_X12  + SZ_X12;
constexpr size_t OFF_Y    = OFF_G    + SZ_G;
constexpr size_t OFF_SC   = OFF_Y    + SZ_Y;
constexpr size_t SCRATCH_TOTAL = OFF_SC + SZ_SC;

__device__ float g_scratch[SCRATCH_TOTAL];

// ---------------- generic batched GEMM ----------------
// C[m,n] = act( sum_k A[m,k] * W[n,k] + bias[n] )                (gate==nullptr)
// C[m,n] += gate[(m>>10)*gateStride + n] * (sum_k ... + bias[n]) (gate!=nullptr)
// A addr:  A + m*lda + k
// W addr:  W + n*ldbn + k*ldbk
// batch z: base += (z/zdiv)*s1 + (z%zdiv)*s2   (per-operand)
__global__ __launch_bounds__(256) void gemm_kernel(
    const float* __restrict__ A, const float* __restrict__ Wm,
    const float* __restrict__ bias, float* __restrict__ C,
    const float* __restrict__ gate, int gateStride,
    int M, int Nc, int K,
    long long lda, long long ldbn, long long ldbk, long long ldc,
    int zdiv,
    long long as1, long long as2, long long bs1, long long bs2,
    long long cs1, long long cs2,
    int act)
{
    __shared__ float As[8][129];
    __shared__ float Bs[8][129];

    int z  = blockIdx.z;
    long long bq = z / zdiv, rq = z % zdiv;
    const float* Ab = A  + bq * as1 + rq * as2;
    const float* Wb = Wm + bq * bs1 + rq * bs2;
    float*       Cb = C  + bq * cs1 + rq * cs2;

    int m0 = blockIdx.y * 128;
    int n0 = blockIdx.x * 128;
    int t  = threadIdx.x;
    int tx = t & 15, ty = t >> 4;

    float acc[8][8];
    #pragma unroll
    for (int i = 0; i < 8; i++)
        #pragma unroll
        for (int j = 0; j < 8; j++) acc[i][j] = 0.f;

    for (int k0 = 0; k0 < K; k0 += 8) {
        #pragma unroll
        for (int s = 0; s < 4; s++) {
            int idx = t + s * 256;
            int kk = idx & 7, mm = idx >> 3;
            int gm = m0 + mm, gk = k0 + kk;
            As[kk][mm] = (gm < M && gk < K) ? Ab[(long long)gm * lda + gk] : 0.f;
            int gn = n0 + mm;
            Bs[kk][mm] = (gn < Nc && gk < K)
                       ? Wb[(long long)gn * ldbn + (long long)gk * ldbk] : 0.f;
        }
        __syncthreads();
        #pragma unroll
        for (int kk = 0; kk < 8; kk++) {
            float a[8], b[8];
            #pragma unroll
            for (int i = 0; i < 8; i++) a[i] = As[kk][ty + 16 * i];
            #pragma unroll
            for (int j = 0; j < 8; j++) b[j] = Bs[kk][tx + 16 * j];
            #pragma unroll
            for (int i = 0; i < 8; i++)
                #pragma unroll
                for (int j = 0; j < 8; j++) acc[i][j] += a[i] * b[j];
        }
        __syncthreads();
    }

    #pragma unroll
    for (int i = 0; i < 8; i++) {
        int row = m0 + ty + 16 * i;
        if (row >= M) continue;
        int bidx = row >> 10;
        #pragma unroll
        for (int j = 0; j < 8; j++) {
            int col = n0 + tx + 16 * j;
            if (col >= Nc) continue;
            float v = acc[i][j] + (bias ? bias[col] : 0.f);
            long long ci = (long long)row * ldc + col;
            if (gate) {
                Cb[ci] += gate[bidx * gateStride + col] * v;
            } else {
                if (act == 1) v = v / (1.f + expf(-v));   // silu
                Cb[ci] = v;
            }
        }
    }
}

// ---------------- timestep embedding ----------------
__global__ void temb_kernel(const float* __restrict__ t, float* __restrict__ temb)
{
    int b = blockIdx.x, i = threadIdx.x;          // i in [0,256)
    float tv = t[b];
    int d = i & 127;
    float fr = expf(-logf(10000.f) * (float)d / 128.f);
    float a = tv * fr;
    temb[b * 256 + i] = (i < 128) ? cosf(a) : sinf(a);
}

// ---------------- patch embed + pos embed ----------------
__global__ void patch_kernel(const float* __restrict__ x,
                             const float* __restrict__ pw,
                             const float* __restrict__ pb,
                             float* __restrict__ h)
{
    int row = blockIdx.x;              // b*1024 + n
    int b = row >> 10, n = row & 1023;
    int hp = n >> 4, wp = n & 15;
    int t = threadIdx.x;

    __shared__ float xs[32];
    if (t < 32) {
        int c = t >> 4, p = (t >> 2) & 3, q = t & 3;
        xs[t] = x[((long long)(b * 2 + c) * 256 + hp * 4 + p) * 64 + wp * 4 + q];
    }
    __syncthreads();

    #pragma unroll
    for (int i = 0; i < 4; i++) {
        int o = t + 256 * i;
        float acc = pb[o];
        #pragma unroll
        for (int j = 0; j < 32; j++) acc += xs[j] * pw[o * 32 + j];
        int r = o >> 8, dd = o & 255;
        float omega = expf(-(float)dd * (logf(10000.f) / 256.f));
        float pos = (r < 2) ? (float)wp : (float)hp;
        float ang = pos * omega;
        acc += (r & 1) ? cosf(ang) : sinf(ang);
        h[(long long)row * 1024 + o] = acc;
    }
}

// ---------------- rmsnorm + modulate ----------------
__global__ void rmsmod_kernel(const float* __restrict__ H, float* __restrict__ Hn,
                              const float* __restrict__ nw,
                              const float* __restrict__ shiftB,
                              const float* __restrict__ scaleB, int adaStride)
{
    int row = blockIdx.x;
    int b = row >> 10;
    int t = threadIdx.x;
    const float* xr = H + (long long)row * 1024;
    float v0 = xr[t], v1 = xr[t + 256], v2 = xr[t + 512], v3 = xr[t + 768];
    float ss = v0 * v0 + v1 * v1 + v2 * v2 + v3 * v3;

    __shared__ float sh[256];
    sh[t] = ss; __syncthreads();
    for (int o = 128; o > 0; o >>= 1) { if (t < o) sh[t] += sh[t + o]; __syncthreads(); }
    float rinv = rsqrtf(sh[0] * (1.f / 1024.f) + kEPS);

    const float* shv = shiftB + (long long)b * adaStride;
    const float* scv = scaleB + (long long)b * adaStride;
    float* y = Hn + (long long)row * 1024;
    y[t]       = v0 * rinv * nw[t]       * (1.f + scv[t])       + shv[t];
    y[t + 256] = v1 * rinv * nw[t + 256] * (1.f + scv[t + 256]) + shv[t + 256];
    y[t + 512] = v2 * rinv * nw[t + 512] * (1.f + scv[t + 512]) + shv[t + 512];
    y[t + 768] = v3 * rinv * nw[t + 768] * (1.f + scv[t + 768]) + shv[t + 768];
}

// ---------------- per-head q/k rmsnorm + rope (one warp per head-row) -------
__global__ void qkrope_kernel(float* __restrict__ qkv,
                              const float* __restrict__ qn,
                              const float* __restrict__ kn)
{
    int task = blockIdx.x * 8 + (threadIdx.x >> 5);   // 262144 tasks
    int lane = threadIdx.x & 31;
    int token = task >> 5;
    int r = task & 31;
    int which = r >> 4;        // 0=q 1=k
    int head  = r & 15;

    float* p = qkv + (long long)token * 3072 + which * 1024 + head * 64 + 2 * lane;
    float e0 = p[0], e1 = p[1];
    float ss = e0 * e0 + e1 * e1;
    #pragma unroll
    for (int o = 16; o > 0; o >>= 1) ss += __shfl_xor_sync(0xffffffffu, ss, o);
    float rinv = rsqrtf(ss * (1.f / 64.f) + kEPS);

    const float* w = which ? kn : qn;
    float n0 = e0 * rinv * w[2 * lane];
    float n1 = e1 * rinv * w[2 * lane + 1];

    int n = token & 1023;
    int hp = n >> 4, wp = n & 15;
    float pos = (lane < 16) ? (float)hp : (float)wp;
    float fr = expf(-(float)(lane & 15) * (logf(10000.f) / 16.f));
    float ang = pos * fr;
    float c = cosf(ang), s = sinf(ang);
    p[0] = n0 * c - n1 * s;
    p[1] = n1 * c + n0 * s;
}

// ---------------- row softmax with 1/sqrt(HD) scale ----------------
__global__ void softmax_kernel(float* __restrict__ S)
{
    long long row = blockIdx.x;
    float* p = S + row * 1024;
    int t = threadIdx.x;
    float v0 = p[t] * 0.125f, v1 = p[t + 256] * 0.125f,
          v2 = p[t + 512] * 0.125f, v3 = p[t + 768] * 0.125f;
    float mx = fmaxf(fmaxf(v0, v1), fmaxf(v2, v3));

    __shared__ float sh[256];
    sh[t] = mx; __syncthreads();
    for (int o = 128; o > 0; o >>= 1) { if (t < o) sh[t] = fmaxf(sh[t], sh[t + o]); __syncthreads(); }
    mx = sh[0]; __syncthreads();

    float e0 = expf(v0 - mx), e1 = expf(v1 - mx), e2 = expf(v2 - mx), e3 = expf(v3 - mx);
    sh[t] = e0 + e1 + e2 + e3; __syncthreads();
    for (int o = 128; o > 0; o >>= 1) { if (t < o) sh[t] += sh[t + o]; __syncthreads(); }
    float inv = 1.f / sh[0];
    p[t] = e0 * inv; p[t + 256] = e1 * inv; p[t + 512] = e2 * inv; p[t + 768] = e3 * inv;
}

// ---------------- swiglu ----------------
__global__ void swiglu_kernel(const float* __restrict__ x12, float* __restrict__ g)
{
    int row = blockIdx.y;
    int j = blockIdx.x * 256 + threadIdx.x;
    if (j >= kFFN) return;
    float a  = x12[(long long)row * 5460 + j];
    float b2 = x12[(long long)row * 5460 + kFFN + j];
    g[(long long)row * kFFN + j] = (a / (1.f + expf(-a))) * b2;
}

// ---------------- unpatchify ----------------
__global__ void unpatch_kernel(const float* __restrict__ y, float* __restrict__ out)
{
    int idx = blockIdx.x * 256 + threadIdx.x;      // < 262144
    int ww = idx & 63;
    int hh = (idx >> 6) & 255;
    int c  = (idx >> 14) & 1;
    int b  = idx >> 15;
    int hp = hh >> 2, p = hh & 3, wp = ww >> 2, q = ww & 3;
    out[idx] = y[((long long)(b * 1024 + hp * 16 + wp)) * 32 + (p * 4 + q) * 2 + c];
}

// ---------------- host-side gemm helper ----------------
static void gemm(const float* A, const float* Wm, const float* bias, float* C,
                 int M, int Nc, int K,
                 long long lda, long long ldbn, long long ldbk, long long ldc,
                 int batches = 1, int zdiv = 1,
                 long long as1 = 0, long long as2 = 0,
                 long long bs1 = 0, long long bs2 = 0,
                 long long cs1 = 0, long long cs2 = 0,
                 const float* gate = nullptr, int gateStride = 0, int act = 0)
{
    dim3 grid((Nc + 127) / 128, (M + 127) / 128, batches);
    gemm_kernel<<<grid, 256>>>(A, Wm, bias, C, gate, gateStride,
                               M, Nc, K, lda, ldbn, ldbk, ldc,
                               zdiv, as1, as2, bs1, bs2, cs1, cs2, act);
}

// ---------------- driver ----------------
extern "C" void kernel_launch(void* const* d_in, const int* /*in_sizes*/, int /*n_in*/,
                              void* d_out, int /*out_size*/)
{
    const float* x       = (const float*)d_in[0];
    const float* t       = (const float*)d_in[1];
    const float* patch_w = (const float*)d_in[2];
    const float* patch_b = (const float*)d_in[3];
    const float* t_w     = (const float*)d_in[4];
    const float* t_b     = (const float*)d_in[5];
    const float* norm1_w = (const float*)d_in[6];
    const float* qkv_w   = (const float*)d_in[7];
    const float* qkv_b   = (const float*)d_in[8];
    const float* qn_w    = (const float*)d_in[9];
    const float* kn_w    = (const float*)d_in[10];
    const float* proj_w  = (const float*)d_in[11];
    const float* proj_b  = (const float*)d_in[12];
    const float* norm2_w = (const float*)d_in[13];
    const float* w12_w   = (const float*)d_in[14];
    const float* w12_b   = (const float*)d_in[15];
    const float* w3_w    = (const float*)d_in[16];
    const float* w3_b    = (const float*)d_in[17];
    const float* ada_w   = (const float*)d_in[18];
    const float* ada_b   = (const float*)d_in[19];
    const float* fnorm_w = (const float*)d_in[20];
    const float* flin_w  = (const float*)d_in[21];
    const float* flin_b  = (const float*)d_in[22];
    const float* fada_w  = (const float*)d_in[23];
    const float* fada_b  = (const float*)d_in[24];
    float* out = (float*)d_out;

    float* base = nullptr;
    cudaGetSymbolAddress((void**)&base, g_scratch);
    float* temb = base + OFF_TEMB;
    float* cs   = base + OFF_CS;
    float* ada  = base + OFF_ADA;
    float* fada = base + OFF_FADA;
    float* h    = base + OFF_H;
    float* hn   = base + OFF_HN;
    float* qkv  = base + OFF_QKV;
    float* o    = base + OFF_O;
    float* x12  = base + OFF_X12;
    float* g    = base + OFF_G;
    float* y    = base + OFF_Y;
    float* sc   = base + OFF_SC;

    // conditioning
    temb_kernel<<<8, 256>>>(t, temb);
    gemm(temb, t_w, t_b, cs, 8, 1024, 256, 256, 256, 1, 1024,
         1, 1, 0, 0, 0, 0, 0, 0, nullptr, 0, /*act=silu*/1);

    // patch embed + pos embed
    patch_kernel<<<8192, 256>>>(x, patch_w, patch_b, h);

    for (int d = 0; d < 8; d++) {
        const float* adw = ada_w + (size_t)d * 6144 * 1024;
        // ada = cs @ ada_w^T + ada_b
        gemm(cs, adw, ada_b + d * 6144, ada, 8, 6144, 1024, 1024, 1024, 1, 6144);

        // hn = modulate(rmsnorm(h, norm1), sm, scm)
        rmsmod_kernel<<<8192, 256>>>(h, hn, norm1_w + d * 1024, ada, ada + 1024, 6144);

        // qkv
        gemm(hn, qkv_w + (size_t)d * 3072 * 1024, qkv_b + d * 3072, qkv,
             8192, 3072, 1024, 1024, 1024, 1, 3072);

        // per-head rmsnorm + rope on q,k
        qkrope_kernel<<<32768, 256>>>(qkv, qn_w + d * 64, kn_w + d * 64);

        // scores = Q @ K^T   (batched over 128 (b,head))
        gemm(qkv, qkv + 1024, nullptr, sc,
             1024, 1024, 64, 3072, 3072, 1, 1024,
             128, 16,
             1024LL * 3072, 64, 1024LL * 3072, 64,
             16LL << 20, 1LL << 20);

        softmax_kernel<<<131072, 256>>>(sc);

        // o = P @ V
        gemm(sc, qkv + 2048, nullptr, o,
             1024, 64, 1024, 1024, 1, 3072, 1024,
             128, 16,
             16LL << 20, 1LL << 20,
             1024LL * 3072, 64,
             1024LL * 1024, 64);

        // h += gm * (o @ proj^T + proj_b)
        gemm(o, proj_w + (size_t)d * 1024 * 1024, proj_b + d * 1024, h,
             8192, 1024, 1024, 1024, 1024, 1, 1024,
             1, 1, 0, 0, 0, 0, 0, 0, ada + 2048, 6144);

        // hn = modulate(rmsnorm(h, norm2), sp, scp)
        rmsmod_kernel<<<8192, 256>>>(h, hn, norm2_w + d * 1024, ada + 3072, ada + 4096, 6144);

        // x12 = hn @ w12^T + b
        gemm(hn, w12_w + (size_t)d * 5460 * 1024, w12_b + d * 5460, x12,
             8192, 5460, 1024, 1024, 1024, 1, 5460);

        // g = silu(x1) * x2
        swiglu_kernel<<<dim3(11, 8192), 256>>>(x12, g);

        // h += gp * (g @ w3^T + b)
        gemm(g, w3_w + (size_t)d * 1024 * 2730, w3_b + d * 1024, h,
             8192, 1024, 2730, 2730, 2730, 1, 1024,
             1, 1, 0, 0, 0, 0, 0, 0, ada + 5120, 6144);
    }

    // final adaLN + linear + unpatchify
    gemm(cs, fada_w, fada_b, fada, 8, 2048, 1024, 1024, 1024, 1, 2048);
    rmsmod_kernel<<<8192, 256>>>(h, hn, fnorm_w, fada, fada + 1024, 2048);
    gemm(hn, flin_w, flin_b, y, 8192, 32, 1024, 1024, 1024, 1, 32);
    unpatch_kernel<<<1024, 256>>>(y, out);
}

// round 4
// speedup vs baseline: 2.0490x; 2.0490x over previous
#include <cuda_runtime.h>
#include <cuda_bf16.h>
#include <cstdint>
#include <math.h>

using bf16 = __nv_bfloat16;
constexpr float kEPS = 1e-6f;
constexpr int kFFN = 2730, kFFNP = 2752;

// ---------- helpers ----------
__device__ __forceinline__ uint32_t smem_u32(const void* p){
    uint32_t a;
    asm("{ .reg .u64 t; cvta.to.shared.u64 t, %1; cvt.u32.u64 %0, t; }" : "=r"(a) : "l"(p));
    return a;
}
#define CPA(dst, src, sz) \
    asm volatile("cp.async.cg.shared.global [%0], [%1], 16, %2;" :: "r"(dst), "l"(src), "r"(sz) : "memory")
#define CP_COMMIT() asm volatile("cp.async.commit_group;" ::: "memory")
#define CP_WAIT1()  asm volatile("cp.async.wait_group 1;" ::: "memory")
#define LDMX4(r0,r1,r2,r3, addr) \
    asm volatile("ldmatrix.sync.aligned.m8n8.x4.shared.b16 {%0,%1,%2,%3}, [%4];" \
        : "=r"(r0), "=r"(r1), "=r"(r2), "=r"(r3) : "r"(addr))
#define MMA(d, a, b0, b1) \
    asm volatile("mma.sync.aligned.m16n8k16.row.col.f32.bf16.bf16.f32 " \
        "{%0,%1,%2,%3}, {%4,%5,%6,%7}, {%8,%9}, {%0,%1,%2,%3};" \
        : "+f"((d)[0]), "+f"((d)[1]), "+f"((d)[2]), "+f"((d)[3]) \
        : "r"((a)[0]), "r"((a)[1]), "r"((a)[2]), "r"((a)[3]), "r"(b0), "r"(b1))

__device__ __forceinline__ void fsplit(float v, bf16& h, bf16& l){
    h = __float2bfloat16(v);
    l = __float2bfloat16(v - __bfloat162float(h));
}

// ---------- scratch layout (bytes) ----------
constexpr size_t ALN(size_t x){ return (x + 1023) & ~(size_t)1023; }
constexpr size_t O_H    = 0;
constexpr size_t O_QKV  = ALN(O_H    + 8192ull*1024*4);
constexpr size_t O_SC   = ALN(O_QKV  + 8192ull*3072*4);     // scores fp32; also aliases x12
constexpr size_t O_O    = ALN(O_SC   + 128ull*1024*1024*4);
constexpr size_t O_Y    = ALN(O_O    + 8192ull*1024*4);
constexpr size_t O_TEMB = ALN(O_Y    + 8192ull*32*4);
constexpr size_t O_CS   = ALN(O_TEMB + 8ull*256*4);
constexpr size_t O_ADA  = ALN(O_CS   + 8ull*1024*4);
constexpr size_t O_FADA = ALN(O_ADA  + 8ull*6144*4);
constexpr size_t O_HNH  = ALN(O_FADA + 8ull*2048*4);
constexpr size_t O_HNL  = ALN(O_HNH + 8192ull*1024*2);
constexpr size_t O_QH   = ALN(O_HNL + 8192ull*1024*2);
constexpr size_t O_QL   = ALN(O_QH  + 8192ull*1024*2);
constexpr size_t O_KH   = ALN(O_QL  + 8192ull*1024*2);
constexpr size_t O_KL   = ALN(O_KH  + 8192ull*1024*2);
constexpr size_t O_VTH  = ALN(O_KL  + 8192ull*1024*2);
constexpr size_t O_VTL  = ALN(O_VTH + 8192ull*1024*2);
constexpr size_t O_PH   = ALN(O_VTL + 8192ull*1024*2);
constexpr size_t O_PL   = ALN(O_PH  + 128ull*1024*1024*2);
constexpr size_t O_GH   = ALN(O_PL  + 128ull*1024*1024*2);
constexpr size_t O_GL   = ALN(O_GH  + 8192ull*kFFNP*2);
constexpr size_t O_OH   = ALN(O_GL  + 8192ull*kFFNP*2);
constexpr size_t O_OL   = ALN(O_OH  + 8192ull*1024*2);
constexpr size_t O_WQH  = ALN(O_OL  + 8192ull*1024*2);
constexpr size_t O_WQL  = ALN(O_WQH + 24576ull*1024*2);
constexpr size_t O_WPH  = ALN(O_WQL + 24576ull*1024*2);
constexpr size_t O_WPL  = ALN(O_WPH + 8192ull*1024*2);
constexpr size_t O_W12H = ALN(O_WPL + 8192ull*1024*2);
constexpr size_t O_W12L = ALN(O_W12H+ 43680ull*1024*2);
constexpr size_t O_W3H  = ALN(O_W12L+ 43680ull*1024*2);
constexpr size_t O_W3L  = ALN(O_W3H + 8192ull*kFFNP*2);
constexpr size_t O_WFH  = ALN(O_W3L + 8192ull*kFFNP*2);
constexpr size_t O_WFL  = ALN(O_WFH + 32ull*1024*2);
constexpr size_t SCRATCH_BYTES = ALN(O_WFL + 32ull*1024*2);

__device__ __align__(1024) unsigned char g_scratch[SCRATCH_BYTES];

// ---------- warp-MMA GEMM (bf16 hi/lo 3-term split, fp32 accum) ----------
// CTA tile 128(M) x 256(N) x 32(K-chunk); 8 warps 2x4, warp tile 64x64.
// C[m,n] (+)= [gate[b][n]] * ( sum_k A[m,k]*B[n,k] + bias[n] )
// SMEM per stage: Ah(10240) Al(10240) Bh(20480) Bl(20480) = 61440 B; 3 stages.
constexpr int GK_STAGE = 61440;
constexpr int GK_SMEM  = 3 * GK_STAGE;

__global__ __launch_bounds__(256, 1) void mm_gemm_kernel(
    const bf16* __restrict__ Ah, const bf16* __restrict__ Al,
    const bf16* __restrict__ Bh, const bf16* __restrict__ Bl,
    const float* __restrict__ bias, float* __restrict__ C,
    const float* __restrict__ gate, int gateStride,
    int Nc, int K, long long lda, long long ldb, long long ldc,
    int zdiv, long long as1, long long as2, long long bs1, long long bs2,
    long long cs1, long long cs2)
{
    extern __shared__ char smem[];
    uint32_t sb = smem_u32(smem);
    const int t = threadIdx.x, wid = t >> 5, lane = t & 31;
    const int wm = wid & 1, wn = wid >> 1;

    const int z = blockIdx.z;
    const long long bq = z / zdiv, rq = z % zdiv;
    const bf16* Ahb = Ah + bq*as1 + rq*as2;
    const bf16* Alb = Al + bq*as1 + rq*as2;
    const bf16* Bhb = Bh + bq*bs1 + rq*bs2;
    const bf16* Blb = Bl + bq*bs1 + rq*bs2;
    float* Cb = C + bq*cs1 + rq*cs2;
    const int m0 = blockIdx.y * 128, n0 = blockIdx.x * 256;
    const int nsteps = K >> 5;

    const bf16* pAh = Ahb + (long long)(m0 + t) * lda;   // used only for t<128
    const bf16* pAl = Alb + (long long)(m0 + t) * lda;
    const int gn = n0 + t;
    const uint32_t bsz = (gn < Nc) ? 16u : 0u;
    const bf16* pBh = Bhb + (long long)gn * ldb;
    const bf16* pBl = Blb + (long long)gn * ldb;

    auto stage_load = [&](int ks, int buf) {
        if (ks < nsteps) {
            const int k0 = ks << 5;
            const uint32_t dstA = sb + buf*GK_STAGE + t*80;
            const uint32_t dstB = sb + buf*GK_STAGE + 20480 + t*80;
            if (t < 128) {
                #pragma unroll
                for (int sg = 0; sg < 4; sg++) {
                    CPA(dstA + sg*16,         pAh + k0 + sg*8, 16u);
                    CPA(dstA + 10240 + sg*16, pAl + k0 + sg*8, 16u);
                }
            }
            #pragma unroll
            for (int sg = 0; sg < 4; sg++) {
                CPA(dstB + sg*16,         pBh + k0 + sg*8, bsz);
                CPA(dstB + 20480 + sg*16, pBl + k0 + sg*8, bsz);
            }
        }
        CP_COMMIT();
    };

    float acc[4][8][4];
    #pragma unroll
    for (int i = 0; i < 4; i++)
        #pragma unroll
        for (int j = 0; j < 8; j++)
            #pragma unroll
            for (int k = 0; k < 4; k++) acc[i][j][k] = 0.f;

    stage_load(0, 0);
    stage_load(1, 1);

    // ldmatrix lane base offsets (row stride 80B; conflict-free)
    const uint32_t a_r = (uint32_t)(wm*64 + (lane & 7) + (lane & 8));
    const uint32_t a_c = (uint32_t)(lane & 16);
    const uint32_t b_r = (uint32_t)(wn*64 + (lane & 7) + ((lane & 16) >> 1));
    const uint32_t b_c = (uint32_t)((lane & 8) << 1);

    for (int ks = 0; ks < nsteps; ks++) {
        CP_WAIT1();
        __syncthreads();
        stage_load(ks + 2, (ks + 2) % 3);
        const uint32_t st = sb + (ks % 3) * GK_STAGE;
        #pragma unroll
        for (int kk = 0; kk < 2; kk++) {
            uint32_t aH[4][4], aL[4][4];
            #pragma unroll
            for (int mt = 0; mt < 4; mt++) {
                uint32_t ad = st + (a_r + mt*16)*80 + a_c + kk*32;
                LDMX4(aH[mt][0], aH[mt][1], aH[mt][2], aH[mt][3], ad);
                LDMX4(aL[mt][0], aL[mt][1], aL[mt][2], aL[mt][3], ad + 10240);
            }
            #pragma unroll
            for (int bt = 0; bt < 4; bt++) {
                uint32_t bd = st + 20480 + (b_r + bt*16)*80 + b_c + kk*32;
                uint32_t h0,h1,h2,h3, l0,l1,l2,l3;
                LDMX4(h0,h1,h2,h3, bd);
                LDMX4(l0,l1,l2,l3, bd + 20480);
                #pragma unroll
                for (int mt = 0; mt < 4; mt++) {
                    MMA(acc[mt][2*bt],   aH[mt], h0, h1);
                    MMA(acc[mt][2*bt+1], aH[mt], h2, h3);
                    MMA(acc[mt][2*bt],   aH[mt], l0, l1);
                    MMA(acc[mt][2*bt+1], aH[mt], l2, l3);
                    MMA(acc[mt][2*bt],   aL[mt], h0, h1);
                    MMA(acc[mt][2*bt+1], aL[mt], h2, h3);
                }
            }
        }
    }

    // epilogue: direct float2 stores with bias / gated residual
    const bool gated = (gate != nullptr);
    #pragma unroll
    for (int mt = 0; mt < 4; mt++) {
        const int r0 = m0 + wm*64 + mt*16 + (lane >> 2);
        #pragma unroll
        for (int half = 0; half < 2; half++) {
            const int row = r0 + half*8;
            const int bidx = row >> 10;
            float* crow = Cb + (long long)row * ldc;
            const float* grow = gated ? gate + (long long)bidx * gateStride : nullptr;
            #pragma unroll
            for (int nt = 0; nt < 8; nt++) {
                const int col = n0 + wn*64 + nt*8 + 2*(lane & 3);
                if (col >= Nc) continue;
                float v0 = acc[mt][nt][half*2 + 0];
                float v1 = acc[mt][nt][half*2 + 1];
                if (bias) { v0 += __ldg(bias + col); v1 += __ldg(bias + col + 1); }
                if (gated) {
                    float2 old = *(float2*)(crow + col);
                    v0 = old.x + __ldg(grow + col)     * v0;
                    v1 = old.y + __ldg(grow + col + 1) * v1;
                }
                *(float2*)(crow + col) = make_float2(v0, v1);
            }
        }
    }
}

// ---------- small-M (M=8) fp32 GEMM: Y = act(X @ W^T + b) ----------
__global__ __launch_bounds__(256) void smallm_kernel(
    const float* __restrict__ X, const float* __restrict__ W,
    const float* __restrict__ bias, float* __restrict__ Y,
    int Nc, int K, int act)
{
    __shared__ float xs[8 * 1024];
    int t = threadIdx.x;
    for (int i = t; i < 8 * K / 4; i += 256)
        ((float4*)xs)[i] = ((const float4*)X)[i];
    __syncthreads();
    int w = t >> 5, lane = t & 31;
    for (int j = 0; j < 8; j++) {
        int n = blockIdx.x * 64 + w * 8 + j;
        float acc[8];
        #pragma unroll
        for (int b = 0; b < 8; b++) acc[b] = 0.f;
        const float4* wr = (const float4*)(W + (size_t)n * K);
        for (int k4 = lane; k4 < K / 4; k4 += 32) {
            float4 wv = wr[k4];
            #pragma unroll
            for (int b = 0; b < 8; b++) {
                float4 cv = ((const float4*)(xs + b * K))[k4];
                acc[b] += wv.x*cv.x + wv.y*cv.y + wv.z*cv.z + wv.w*cv.w;
            }
        }
        #pragma unroll
        for (int o = 16; o > 0; o >>= 1)
            #pragma unroll
            for (int b = 0; b < 8; b++)
                acc[b] += __shfl_xor_sync(0xffffffffu, acc[b], o);
        if (lane < 8) {
            float v = acc[lane] + bias[n];
            if (act == 1) v = v / (1.f + expf(-v));
            Y[lane * Nc + n] = v;
        }
    }
}

// ---------- split fp32 -> bf16 hi/lo (with optional zero pad) ----------
__global__ void splitpad_kernel(const float* __restrict__ src,
                                bf16* __restrict__ hi, bf16* __restrict__ lo,
                                int srcld, int dstld)
{
    int r = blockIdx.y;
    int c = blockIdx.x * 256 + threadIdx.x;
    if (c >= dstld) return;
    float v = (c < srcld) ? src[(long long)r * srcld + c] : 0.f;
    bf16 h, l; fsplit(v, h, l);
    long long o = (long long)r * dstld + c;
    hi[o] = h; lo[o] = l;
}

// ---------- elementwise kernels ----------
__global__ void temb_kernel(const float* __restrict__ t, float* __restrict__ temb)
{
    int b = blockIdx.x, i = threadIdx.x;
    float tv = t[b];
    int d = i & 127;
    float fr = expf(-logf(10000.f) * (float)d / 128.f);
    float a = tv * fr;
    temb[b * 256 + i] = (i < 128) ? cosf(a) : sinf(a);
}

__global__ void patch_kernel(const float* __restrict__ x, const float* __restrict__ pw,
                             const float* __restrict__ pb, float* __restrict__ h)
{
    int row = blockIdx.x;
    int b = row >> 10, n = row & 1023;
    int hp = n >> 4, wp = n & 15;
    int t = threadIdx.x;
    __shared__ float xs[32];
    if (t < 32) {
        int c = t >> 4, p = (t >> 2) & 3, q = t & 3;
        xs[t] = x[((long long)(b * 2 + c) * 256 + hp * 4 + p) * 64 + wp * 4 + q];
    }
    __syncthreads();
    #pragma unroll
    for (int i = 0; i < 4; i++) {
        int o = t + 256 * i;
        float acc = pb[o];
        #pragma unroll
        for (int j = 0; j < 32; j++) acc += xs[j] * pw[o * 32 + j];
        int r = o >> 8, dd = o & 255;
        float omega = expf(-(float)dd * (logf(10000.f) / 256.f));
        float pos = (r < 2) ? (float)wp : (float)hp;
        float ang = pos * omega;
        acc += (r & 1) ? cosf(ang) : sinf(ang);
        h[(long long)row * 1024 + o] = acc;
    }
}

__global__ void rmsmod_kernel(const float* __restrict__ H,
                              bf16* __restrict__ Oh, bf16* __restrict__ Ol,
                              const float* __restrict__ nw,
                              const float* __restrict__ shiftB,
                              const float* __restrict__ scaleB, int adaStride)
{
    int row = blockIdx.x;
    int b = row >> 10;
    int t = threadIdx.x;
    const float* xr = H + (long long)row * 1024;
    float v0 = xr[t], v1 = xr[t + 256], v2 = xr[t + 512], v3 = xr[t + 768];
    __shared__ float sh[256];
    sh[t] = v0*v0 + v1*v1 + v2*v2 + v3*v3;
    __syncthreads();
    for (int o = 128; o > 0; o >>= 1) { if (t < o) sh[t] += sh[t + o]; __syncthreads(); }
    float rinv = rsqrtf(sh[0] * (1.f / 1024.f) + kEPS);
    const float* shv = shiftB + (long long)b * adaStride;
    const float* scv = scaleB + (long long)b * adaStride;
    long long base = (long long)row * 1024;
    #pragma unroll
    for (int i = 0; i < 4; i++) {
        int c = t + 256 * i;
        float vv = (i == 0 ? v0 : i == 1 ? v1 : i == 2 ? v2 : v3);
        float y = vv * rinv * nw[c] * (1.f + scv[c]) + shv[c];
        bf16 h, l; fsplit(y, h, l);
        Oh[base + c] = h; Ol[base + c] = l;
    }
}

__global__ void qkrope_kernel(const float* __restrict__ qkv,
                              const float* __restrict__ qn, const float* __restrict__ kn,
                              bf16* __restrict__ Qh, bf16* __restrict__ Ql,
                              bf16* __restrict__ Kh, bf16* __restrict__ Kl)
{
    int task = blockIdx.x * 8 + (threadIdx.x >> 5);
    int lane = threadIdx.x & 31;
    int token = task >> 5;
    int r = task & 31;
    int which = r >> 4, head = r & 15;

    const float* p = qkv + (long long)token * 3072 + which * 1024 + head * 64 + 2 * lane;
    float e0 = p[0], e1 = p[1];
    float ss = e0 * e0 + e1 * e1;
    #pragma unroll
    for (int o = 16; o > 0; o >>= 1) ss += __shfl_xor_sync(0xffffffffu, ss, o);
    float rinv = rsqrtf(ss * (1.f / 64.f) + kEPS);
    const float* w = which ? kn : qn;
    float n0 = e0 * rinv * w[2 * lane];
    float n1 = e1 * rinv * w[2 * lane + 1];

    int n = token & 1023;
    int hp = n >> 4, wp = n & 15;
    float pos = (lane < 16) ? (float)hp : (float)wp;
    float fr = expf(-(float)(lane & 15) * (logf(10000.f) / 16.f));
    float ang = pos * fr;
    float c = cosf(ang), s = sinf(ang);
    float r0 = n0 * c - n1 * s;
    float r1 = n1 * c + n0 * s;

    bf16* Hh = which ? Kh : Qh;
    bf16* Ll = which ? Kl : Ql;
    long long o = (long long)token * 1024 + head * 64 + 2 * lane;
    bf16 h0, l0, h1, l1;
    fsplit(r0, h0, l0); fsplit(r1, h1, l1);
    Hh[o] = h0; Hh[o + 1] = h1;
    Ll[o] = l0; Ll[o + 1] = l1;
}

__global__ void vt_kernel(const float* __restrict__ qkv,
                          bf16* __restrict__ Vh, bf16* __restrict__ Vl)
{
    int bx = blockIdx.x;           // 2048 = 128 bh * 16 chunks
    int bh = bx >> 4, chunk = bx & 15;
    int b = bh >> 4, hh = bh & 15;
    int t = threadIdx.x;
    __shared__ float s[64][65];
    #pragma unroll
    for (int i = 0; i < 16; i++) {
        int idx = t + i * 256;
        int tok = idx >> 6, d = idx & 63;
        s[tok][d] = qkv[((long long)(b * 1024 + chunk * 64 + tok)) * 3072 + 2048 + hh * 64 + d];
    }
    __syncthreads();
    #pragma unroll
    for (int i = 0; i < 16; i++) {
        int idx = t + i * 256;
        int d = idx >> 6, tok = idx & 63;
        float v = s[tok][d];
        bf16 h, l; fsplit(v, h, l);
        long long o = ((long long)bh * 64 + d) * 1024 + chunk * 64 + tok;
        Vh[o] = h; Vl[o] = l;
    }
}

__global__ void softmax_kernel(const float* __restrict__ S,
                               bf16* __restrict__ Ph, bf16* __restrict__ Pl)
{
    long long row = blockIdx.x;
    const float* p = S + row * 1024;
    int t = threadIdx.x;
    float v0 = p[t] * 0.125f, v1 = p[t + 256] * 0.125f,
          v2 = p[t + 512] * 0.125f, v3 = p[t + 768] * 0.125f;
    __shared__ float sh[256];
    sh[t] = fmaxf(fmaxf(v0, v1), fmaxf(v2, v3));
    __syncthreads();
    for (int o = 128; o > 0; o >>= 1) { if (t < o) sh[t] = fmaxf(sh[t], sh[t + o]); __syncthreads(); }
    float mx = sh[0]; __syncthreads();
    float e0 = expf(v0 - mx), e1 = expf(v1 - mx), e2 = expf(v2 - mx), e3 = expf(v3 - mx);
    sh[t] = e0 + e1 + e2 + e3; __syncthreads();
    for (int o = 128; o > 0; o >>= 1) { if (t < o) sh[t] += sh[t + o]; __syncthreads(); }
    float inv = 1.f / sh[0];
    long long base = row * 1024;
    #pragma unroll
    for (int i = 0; i < 4; i++) {
        int c = t + 256 * i;
        float e = (i == 0 ? e0 : i == 1 ? e1 : i == 2 ? e2 : e3) * inv;
        bf16 h, l; fsplit(e, h, l);
        Ph[base + c] = h; Pl[base + c] = l;
    }
}

__global__ void swiglu_kernel(const float* __restrict__ x12,
                              bf16* __restrict__ Gh, bf16* __restrict__ Gl)
{
    int row = blockIdx.y;
    int j = blockIdx.x * 256 + threadIdx.x;
    if (j >= kFFNP) return;
    float v = 0.f;
    if (j < kFFN) {
        float a  = x12[(long long)row * 5460 + j];
        float b2 = x12[(long long)row * 5460 + kFFN + j];
        v = (a / (1.f + expf(-a))) * b2;
    }
    bf16 h, l; fsplit(v, h, l);
    long long o = (long long)row * kFFNP + j;
    Gh[o] = h; Gl[o] = l;
}

__global__ void unpatch_kernel(const float* __restrict__ y, float* __restrict__ out)
{
    int idx = blockIdx.x * 256 + threadIdx.x;
    int ww = idx & 63;
    int hh = (idx >> 6) & 255;
    int c  = (idx >> 14) & 1;
    int b  = idx >> 15;
    int hp = hh >> 2, p = hh & 3, wp = ww >> 2, q = ww & 3;
    out[idx] = y[((long long)(b * 1024 + hp * 16 + wp)) * 32 + (p * 4 + q) * 2 + c];
}

// ---------- host helpers ----------
static void mmgemm(const bf16* Ah, const bf16* Al, const bf16* Bh, const bf16* Bl,
                   const float* bias, float* C, int M, int Nc, int K,
                   long long lda, long long ldb, long long ldc,
                   int batches = 1, int zdiv = 1,
                   long long as1 = 0, long long as2 = 0,
                   long long bs1 = 0, long long bs2 = 0,
                   long long cs1 = 0, long long cs2 = 0,
                   const float* gate = nullptr, int gateStride = 0)
{
    dim3 grid((Nc + 255) / 256, M / 128, batches);
    mm_gemm_kernel<<<grid, 256, GK_SMEM>>>(Ah, Al, Bh, Bl, bias, C, gate, gateStride,
        Nc, K, lda, ldb, ldc, zdiv, as1, as2, bs1, bs2, cs1, cs2);
}
static void split(const float* src, bf16* hi, bf16* lo, int rows, int srcld, int dstld)
{
    dim3 grid((dstld + 255) / 256, rows);
    splitpad_kernel<<<grid, 256>>>(src, hi, lo, srcld, dstld);
}

extern "C" void kernel_launch(void* const* d_in, const int*, int, void* d_out, int)
{
    const float* x       = (const float*)d_in[0];
    const float* t       = (const float*)d_in[1];
    const float* patch_w = (const float*)d_in[2];
    const float* patch_b = (const float*)d_in[3];
    const float* t_w     = (const float*)d_in[4];
    const float* t_b     = (const float*)d_in[5];
    const float* norm1_w = (const float*)d_in[6];
    const float* qkv_w   = (const float*)d_in[7];
    const float* qkv_b   = (const float*)d_in[8];
    const float* qn_w    = (const float*)d_in[9];
    const float* kn_w    = (const float*)d_in[10];
    const float* proj_w  = (const float*)d_in[11];
    const float* proj_b  = (const float*)d_in[12];
    const float* norm2_w = (const float*)d_in[13];
    const float* w12_w   = (const float*)d_in[14];
    const float* w12_b   = (const float*)d_in[15];
    const float* w3_w    = (const float*)d_in[16];
    const float* w3_b    = (const float*)d_in[17];
    const float* ada_w   = (const float*)d_in[18];
    const float* ada_b   = (const float*)d_in[19];
    const float* fnorm_w = (const float*)d_in[20];
    const float* flin_w  = (const float*)d_in[21];
    const float* flin_b  = (const float*)d_in[22];
    const float* fada_w  = (const float*)d_in[23];
    const float* fada_b  = (const float*)d_in[24];
    float* out = (float*)d_out;

    cudaFuncSetAttribute(mm_gemm_kernel, cudaFuncAttributeMaxDynamicSharedMemorySize, GK_SMEM);

    unsigned char* base = nullptr;
    cudaGetSymbolAddress((void**)&base, g_scratch);
    float* h    = (float*)(base + O_H);
    float* qkv  = (float*)(base + O_QKV);
    float* sc   = (float*)(base + O_SC);
    float* x12  = (float*)(base + O_SC);   // alias, disjoint lifetime
    float* o    = (float*)(base + O_O);
    float* y    = (float*)(base + O_Y);
    float* temb = (float*)(base + O_TEMB);
    float* cs   = (float*)(base + O_CS);
    float* ada  = (float*)(base + O_ADA);
    float* fada = (float*)(base + O_FADA);
    bf16* hnh = (bf16*)(base + O_HNH); bf16* hnl = (bf16*)(base + O_HNL);
    bf16* qh  = (bf16*)(base + O_QH);  bf16* ql  = (bf16*)(base + O_QL);
    bf16* kh  = (bf16*)(base + O_KH);  bf16* kl  = (bf16*)(base + O_KL);
    bf16* vth = (bf16*)(base + O_VTH); bf16* vtl = (bf16*)(base + O_VTL);
    bf16* ph  = (bf16*)(base + O_PH);  bf16* pl  = (bf16*)(base + O_PL);
    bf16* gh  = (bf16*)(base + O_GH);  bf16* gl  = (bf16*)(base + O_GL);
    bf16* oh  = (bf16*)(base + O_OH);  bf16* ol  = (bf16*)(base + O_OL);
    bf16* wqh = (bf16*)(base + O_WQH); bf16* wql = (bf16*)(base + O_WQL);
    bf16* wph = (bf16*)(base + O_WPH); bf16* wpl = (bf16*)(base + O_WPL);
    bf16* w12h= (bf16*)(base + O_W12H);bf16* w12l= (bf16*)(base + O_W12L);
    bf16* w3h = (bf16*)(base + O_W3H); bf16* w3l = (bf16*)(base + O_W3L);
    bf16* wfh = (bf16*)(base + O_WFH); bf16* wfl = (bf16*)(base + O_WFL);

    // one-time weight splits
    split(qkv_w,  wqh,  wql,  24576, 1024, 1024);
    split(proj_w, wph,  wpl,  8192,  1024, 1024);
    split(w12_w,  w12h, w12l, 43680, 1024, 1024);
    split(w3_w,   w3h,  w3l,  8192,  kFFN, kFFNP);
    split(flin_w, wfh,  wfl,  32,    1024, 1024);

    // conditioning
    temb_kernel<<<8, 256>>>(t, temb);
    smallm_kernel<<<16, 256>>>(temb, t_w, t_b, cs, 1024, 256, 1);

    // patch embed + pos embed
    patch_kernel<<<8192, 256>>>(x, patch_w, patch_b, h);

    for (int d = 0; d < 8; d++) {
        smallm_kernel<<<96, 256>>>(cs, ada_w + (size_t)d * 6144 * 1024,
                                   ada_b + d * 6144, ada, 6144, 1024, 0);

        rmsmod_kernel<<<8192, 256>>>(h, hnh, hnl, norm1_w + d * 1024, ada, ada + 1024, 6144);

        mmgemm(hnh, hnl, wqh + (size_t)d * 3072 * 1024, wql + (size_t)d * 3072 * 1024,
               qkv_b + d * 3072, qkv, 8192, 3072, 1024, 1024, 1024, 3072);

        qkrope_kernel<<<32768, 256>>>(qkv, qn_w + d * 64, kn_w + d * 64, qh, ql, kh, kl);
        vt_kernel<<<2048, 256>>>(qkv, vth, vtl);

        // scores = Q @ K^T  (batched over 128 (b,head))
        mmgemm(qh, ql, kh, kl, nullptr, sc, 1024, 1024, 64, 1024, 1024, 1024,
               128, 16, 1024ll*1024, 64, 1024ll*1024, 64, 16ll<<20, 1ll<<20);

        softmax_kernel<<<131072, 256>>>(sc, ph, pl);

        // o = P @ V^T
        mmgemm(ph, pl, vth, vtl, nullptr, o, 1024, 64, 1024, 1024, 1024, 1024,
               128, 16, 16ll<<20, 1ll<<20, 16ll*64*1024, 64ll*1024, 1024ll*1024, 64);

        split(o, oh, ol, 8192, 1024, 1024);

        // h += gm * (o @ proj^T + b)
        mmgemm(oh, ol, wph + (size_t)d * 1024 * 1024, wpl + (size_t)d * 1024 * 1024,
               proj_b + d * 1024, h, 8192, 1024, 1024, 1024, 1024, 1024,
               1, 1, 0, 0, 0, 0, 0, 0, ada + 2048, 6144);

        rmsmod_kernel<<<8192, 256>>>(h, hnh, hnl, norm2_w + d * 1024, ada + 3072, ada + 4096, 6144);

        mmgemm(hnh, hnl, w12h + (size_t)d * 5460 * 1024, w12l + (size_t)d * 5460 * 1024,
               w12_b + d * 5460, x12, 8192, 5460, 1024, 1024, 1024, 5460);

        swiglu_kernel<<<dim3(11, 8192), 256>>>(x12, gh, gl);

        // h += gp * (g @ w3^T + b)
        mmgemm(gh, gl, w3h + (size_t)d * 1024 * kFFNP, w3l + (size_t)d * 1024 * kFFNP,
               w3_b + d * 1024, h, 8192, 1024, kFFNP, kFFNP, kFFNP, 1024,
               1, 1, 0, 0, 0, 0, 0, 0, ada + 5120, 6144);
    }

    smallm_kernel<<<32, 256>>>(cs, fada_w, fada_b, fada, 2048, 1024, 0);
    rmsmod_kernel<<<8192, 256>>>(h, hnh, hnl, fnorm_w, fada, fada + 1024, 2048);
    mmgemm(hnh, hnl, wfh, wfl, flin_b, y, 8192, 32, 1024, 1024, 1024, 32);
    unpatch_kernel<<<1024, 256>>>(y, out);
}